// round 3
// baseline (speedup 1.0000x reference)
#include <cuda_runtime.h>
#include <cuda_bf16.h>
#include <cstddef>

// LengthRegulator, scatter formulation:
//   Token j of batch b owns output frames [cum[j-1], cum[j]) (clamped to T).
//   K1: per-batch inclusive scan of durations -> g_cum.
//   K2: one warp per token: read row once (coalesced), store it dur times.
//   K3: zero the tail frames [total, T).
// B=16, S=512, H=512 fixed; T derived from out_size.

#define LR_B 16
#define LR_S 512
#define LR_V 128            // float4 per row (H=512)

__device__ int g_cum[LR_B * LR_S];

// ---------------- K1: inclusive scan per batch ----------------
__global__ __launch_bounds__(LR_S)
void lr_scan_kernel(const int* __restrict__ dur)
{
    __shared__ int cum[LR_S];
    const int b   = blockIdx.x;
    const int tid = threadIdx.x;

    cum[tid] = dur[b * LR_S + tid];
    __syncthreads();
#pragma unroll
    for (int off = 1; off < LR_S; off <<= 1) {
        int add = (tid >= off) ? cum[tid - off] : 0;
        __syncthreads();
        cum[tid] += add;
        __syncthreads();
    }
    g_cum[b * LR_S + tid] = cum[tid];
}

// ---------------- K2: scatter, one warp per token ----------------
// Block = 256 threads = 8 warps = 8 tokens. Grid = (S/8, B).
__global__ __launch_bounds__(256)
void lr_scatter_kernel(const float4* __restrict__ x4,
                       float4*       __restrict__ out4,
                       int T)
{
    const int b    = blockIdx.y;
    const int tok  = blockIdx.x * 8 + (threadIdx.x >> 5);
    const int lane = threadIdx.x & 31;

    const int ci    = b * LR_S + tok;
    int end   = g_cum[ci];
    int start = (tok == 0) ? 0 : g_cum[ci - 1];
    if (start >= T) return;
    if (end > T) end = T;
    if (end <= start) return;

    // Load this token's row once: 4 independent LDG.128 per lane.
    const float4* src = x4 + ((size_t)(b * LR_S + tok)) * LR_V + lane;
    float4 v0 = src[0];
    float4 v1 = src[32];
    float4 v2 = src[64];
    float4 v3 = src[96];

    // Store to each owned frame (2KB-aligned, consecutive).
    float4* dst = out4 + ((size_t)b * T + start) * LR_V + lane;
    for (int f = start; f < end; f++, dst += LR_V) {
        dst[0]  = v0;
        dst[32] = v1;
        dst[64] = v2;
        dst[96] = v3;
    }
}

// ---------------- K3: zero tail frames [total, T) ----------------
// Block covers 32 frames (4096 vec4s); 256 threads x 16 vec4. Grid = (T/32, B).
__global__ __launch_bounds__(256)
void lr_tailzero_kernel(float4* __restrict__ out4, int T)
{
    const int b  = blockIdx.y;
    const int f0 = blockIdx.x * 32;

    int total = g_cum[b * LR_S + (LR_S - 1)];
    if (total > T) total = T;
    if (f0 + 32 <= total) return;       // entirely covered by scatter

    const float4 z = make_float4(0.f, 0.f, 0.f, 0.f);
    const int tid = threadIdx.x;
    float4* base = out4 + ((size_t)b * T + f0) * LR_V;

#pragma unroll
    for (int k = 0; k < 16; k++) {
        int p     = k * 256 + tid;      // 0..4095
        int frame = f0 + (p >> 7);
        if (frame >= total && frame < T)
            base[p] = z;
    }
}

// ---------------- generic fallback (any H; unused for this shape) ----------
__global__ void lr_generic_kernel(const float* __restrict__ x,
                                  const int* __restrict__ dur,
                                  float* __restrict__ out,
                                  int S, int H, int T)
{
    // One thread per output element; recompute searchsorted (slow path only).
    size_t i = (size_t)blockIdx.x * blockDim.x + threadIdx.x;
    size_t total = (size_t)LR_B * T * H;
    if (i >= total) return;
    int e = (int)(i % H);
    int t = (int)((i / H) % T);
    int b = (int)(i / ((size_t)T * H));
    int c = 0, idx = S;
    for (int j = 0; j < S; j++) { c += dur[b * S + j]; if (c > t) { idx = j; break; } }
    out[i] = (idx < S) ? x[((size_t)b * S + idx) * H + e] : 0.f;
}

extern "C" void kernel_launch(void* const* d_in, const int* in_sizes, int n_in,
                              void* d_out, int out_size)
{
    const float* x   = (const float*)d_in[0];
    const int*   dur = (const int*)d_in[1];
    float*       out = (float*)d_out;

    const int BS = in_sizes[1];              // B * S = 8192
    const int H  = in_sizes[0] / BS;         // 512
    const int T  = out_size / (LR_B * H);    // 4096
    const int S  = BS / LR_B;

    if (H == 512 && S == LR_S && (T % 32) == 0) {
        lr_scan_kernel<<<LR_B, LR_S>>>(dur);
        dim3 g2(LR_S / 8, LR_B);
        lr_scatter_kernel<<<g2, 256>>>((const float4*)x, (float4*)out, T);
        dim3 g3(T / 32, LR_B);
        lr_tailzero_kernel<<<g3, 256>>>((float4*)out, T);
    } else {
        size_t total = (size_t)out_size;
        int blocks = (int)((total + 255) / 256);
        lr_generic_kernel<<<blocks, 256>>>(x, dur, out, S, H, T);
    }
}

// round 4
// speedup vs baseline: 1.2022x; 1.2022x over previous
#include <cuda_runtime.h>
#include <cuda_bf16.h>
#include <cstddef>

// LengthRegulator, single fused kernel:
//   Each block handles 16 output frames of one batch. Prologue: warp-shuffle
//   inclusive scan of durations[b] (redundant per block, ~600cyc, hidden),
//   binary search of the 16 frame source rows into shared. Body: 8 front-
//   batched LDG.128 per thread (MLP=8) + 8 STG.128. Frames past the total
//   length get zeros (row = -1). B=16, S=512, H=512 fixed; T from out_size.

#define LR_B   16
#define LR_S   512
#define LR_V   128        // float4 per row (H=512)
#define LR_FPB 16         // frames per block
#define LR_THR 256

__global__ __launch_bounds__(LR_THR)
void lr_fused_kernel(const float4* __restrict__ x4,
                     const int*    __restrict__ dur,
                     float4*       __restrict__ out4,
                     int T)
{
    __shared__ int cum[LR_S];
    __shared__ int sh_w[8];
    __shared__ int sidx[LR_FPB];

    const int b    = blockIdx.y;
    const int f0   = blockIdx.x * LR_FPB;
    const int tid  = threadIdx.x;
    const int wid  = tid >> 5;
    const int lane = tid & 31;

    // ---- warp-shuffle inclusive scan of durations[b, :] (512 ints) ----
    // Each thread owns 2 consecutive elements.
    int2 d = reinterpret_cast<const int2*>(dur + b * LR_S)[tid];
    int s  = d.x + d.y;

    int v = s;
#pragma unroll
    for (int off = 1; off < 32; off <<= 1) {
        int n = __shfl_up_sync(0xFFFFFFFFu, v, off);
        if (lane >= off) v += n;
    }
    if (lane == 31) sh_w[wid] = v;
    __syncthreads();
    if (wid == 0 && lane < 8) {
        int w  = sh_w[lane];
        int vv = w;
#pragma unroll
        for (int off = 1; off < 8; off <<= 1) {
            int n = __shfl_up_sync(0xFFu, vv, off);
            if (lane >= off) vv += n;
        }
        sh_w[lane] = vv - w;          // exclusive warp offset
    }
    __syncthreads();
    int incl = v + sh_w[wid];         // inclusive cumsum at element 2*tid+1
    cum[2 * tid + 1] = incl;
    cum[2 * tid]     = incl - d.y;
    __syncthreads();

    // ---- searchsorted(right) for this block's 16 frames ----
    if (tid < LR_FPB) {
        int t = f0 + tid;
        int lo = 0, hi = LR_S;
        while (lo < hi) {
            int mid = (lo + hi) >> 1;
            if (cum[mid] <= t) lo = mid + 1; else hi = mid;
        }
        sidx[tid] = (lo < LR_S) ? (b * LR_S + lo) : -1;
    }
    __syncthreads();

    // ---- copy: 16 frames x 128 vec4 = 2048 vec4; 8 per thread ----
    float4 val[8];
#pragma unroll
    for (int k = 0; k < 8; k++) {
        int p   = k * LR_THR + tid;       // 0..2047
        int fl  = p >> 7;                 // local frame 0..15
        int e   = p & 127;                // vec4 within row
        int row = sidx[fl];
        val[k] = make_float4(0.f, 0.f, 0.f, 0.f);
        if (row >= 0)
            val[k] = __ldg(&x4[(size_t)row * LR_V + e]);
    }
    float4* base = out4 + ((size_t)b * T + f0) * LR_V;
#pragma unroll
    for (int k = 0; k < 8; k++)
        base[k * LR_THR + tid] = val[k];
}

// ---------------- generic fallback (any shape; unused here) ----------------
__global__ void lr_generic_kernel(const float* __restrict__ x,
                                  const int* __restrict__ dur,
                                  float* __restrict__ out,
                                  int B, int S, int H, int T)
{
    size_t i = (size_t)blockIdx.x * blockDim.x + threadIdx.x;
    size_t total = (size_t)B * T * H;
    if (i >= total) return;
    int e = (int)(i % H);
    int t = (int)((i / H) % T);
    int b = (int)(i / ((size_t)T * H));
    int c = 0, idx = S;
    for (int j = 0; j < S; j++) { c += dur[b * S + j]; if (c > t) { idx = j; break; } }
    out[i] = (idx < S) ? x[((size_t)b * S + idx) * H + e] : 0.f;
}

extern "C" void kernel_launch(void* const* d_in, const int* in_sizes, int n_in,
                              void* d_out, int out_size)
{
    const float* x   = (const float*)d_in[0];
    const int*   dur = (const int*)d_in[1];
    float*       out = (float*)d_out;

    const int BS = in_sizes[1];              // B * S = 8192
    const int H  = in_sizes[0] / BS;         // 512
    const int T  = out_size / (LR_B * H);    // 4096
    const int S  = BS / LR_B;

    if (H == 512 && S == LR_S && (T % LR_FPB) == 0) {
        dim3 grid(T / LR_FPB, LR_B);
        lr_fused_kernel<<<grid, LR_THR>>>((const float4*)x, dur,
                                          (float4*)out, T);
    } else {
        size_t total = (size_t)out_size;
        int blocks = (int)((total + 255) / 256);
        lr_generic_kernel<<<blocks, 256>>>(x, dur, out, LR_B, S, H, T);
    }
}

// round 10
// speedup vs baseline: 1.4040x; 1.1679x over previous
#include <cuda_runtime.h>
#include <cuda_bf16.h>
#include <cstddef>

// LengthRegulator, single fused kernel (R5 theory, sixth submission — five
// prior attempts hit infra GPUAcquisitionTimeout before running):
//   Block = 16 output frames of one batch, 256 threads.
//   Prologue: warp-shuffle inclusive scan of durations[b] + binary search of
//   the 16 frame source rows into shared.
//   Copy: thread owns column e of 8 CONSECUTIVE frames (L1 line reuse across
//   its loads), stores via __stcs (streaming, evict-first: output is
//   write-once). Frames past total length -> zeros.
// B=16, S=512, H=512 fixed; T derived from out_size.

#define LR_B   16
#define LR_S   512
#define LR_V   128        // float4 per row (H=512)
#define LR_FPB 16         // frames per block
#define LR_THR 256

__global__ __launch_bounds__(LR_THR)
void lr_fused_kernel(const float4* __restrict__ x4,
                     const int*    __restrict__ dur,
                     float4*       __restrict__ out4,
                     int T)
{
    __shared__ int cum[LR_S];
    __shared__ int sh_w[8];
    __shared__ int sidx[LR_FPB];

    const int b    = blockIdx.y;
    const int f0   = blockIdx.x * LR_FPB;
    const int tid  = threadIdx.x;
    const int wid  = tid >> 5;
    const int lane = tid & 31;

    // ---- warp-shuffle inclusive scan of durations[b, :] (512 ints) ----
    // Each thread owns 2 consecutive elements.
    int2 d = reinterpret_cast<const int2*>(dur + b * LR_S)[tid];
    int v  = d.x + d.y;
#pragma unroll
    for (int off = 1; off < 32; off <<= 1) {
        int n = __shfl_up_sync(0xFFFFFFFFu, v, off);
        if (lane >= off) v += n;
    }
    if (lane == 31) sh_w[wid] = v;
    __syncthreads();
    if (wid == 0 && lane < 8) {
        int w  = sh_w[lane];
        int vv = w;
#pragma unroll
        for (int off = 1; off < 8; off <<= 1) {
            int n = __shfl_up_sync(0xFFu, vv, off);
            if (lane >= off) vv += n;
        }
        sh_w[lane] = vv - w;          // exclusive warp offset
    }
    __syncthreads();
    int incl = v + sh_w[wid];         // inclusive cumsum at element 2*tid+1
    cum[2 * tid + 1] = incl;
    cum[2 * tid]     = incl - d.y;
    __syncthreads();

    // ---- searchsorted(right) for this block's 16 frames ----
    if (tid < LR_FPB) {
        int t = f0 + tid;
        int lo = 0, hi = LR_S;
        while (lo < hi) {
            int mid = (lo + hi) >> 1;
            if (cum[mid] <= t) lo = mid + 1; else hi = mid;
        }
        sidx[tid] = (lo < LR_S) ? (b * LR_S + lo) : -1;
    }
    __syncthreads();

    // ---- copy: thread = column e of 8 consecutive frames ----
    // g in {0,1}: frames [g*8, g*8+8). Consecutive frames share source rows
    // (avg duration ~7.5) -> most of the 8 loads are L1 same-line hits.
    const int g = tid >> 7;           // 0..1
    const int e = tid & 127;          // vec4 column within row

    float4 val[8];
#pragma unroll
    for (int j = 0; j < 8; j++) {
        int row = sidx[g * 8 + j];
        val[j] = make_float4(0.f, 0.f, 0.f, 0.f);
        if (row >= 0)
            val[j] = __ldg(&x4[(size_t)row * LR_V + e]);
    }

    float4* base = out4 + ((size_t)b * T + f0) * LR_V;
#pragma unroll
    for (int j = 0; j < 8; j++)
        __stcs(&base[(g * 8 + j) * LR_V + e], val[j]);   // streaming store
}

// ---------------- generic fallback (any shape; unused here) ----------------
__global__ void lr_generic_kernel(const float* __restrict__ x,
                                  const int* __restrict__ dur,
                                  float* __restrict__ out,
                                  int B, int S, int H, int T)
{
    size_t i = (size_t)blockIdx.x * blockDim.x + threadIdx.x;
    size_t total = (size_t)B * T * H;
    if (i >= total) return;
    int e = (int)(i % H);
    int t = (int)((i / H) % T);
    int b = (int)(i / ((size_t)T * H));
    int c = 0, idx = S;
    for (int j = 0; j < S; j++) { c += dur[b * S + j]; if (c > t) { idx = j; break; } }
    out[i] = (idx < S) ? x[((size_t)b * S + idx) * H + e] : 0.f;
}

extern "C" void kernel_launch(void* const* d_in, const int* in_sizes, int n_in,
                              void* d_out, int out_size)
{
    const float* x   = (const float*)d_in[0];
    const int*   dur = (const int*)d_in[1];
    float*       out = (float*)d_out;

    const int BS = in_sizes[1];              // B * S = 8192
    const int H  = in_sizes[0] / BS;         // 512
    const int T  = out_size / (LR_B * H);    // 4096
    const int S  = BS / LR_B;

    if (H == 512 && S == LR_S && (T % LR_FPB) == 0) {
        dim3 grid(T / LR_FPB, LR_B);
        lr_fused_kernel<<<grid, LR_THR>>>((const float4*)x, dur,
                                          (float4*)out, T);
    } else {
        size_t total = (size_t)out_size;
        int blocks = (int)((total + 255) / 256);
        lr_generic_kernel<<<blocks, 256>>>(x, dur, out, LR_B, S, H, T);
    }
}

// round 12
// speedup vs baseline: 1.4442x; 1.0286x over previous
#include <cuda_runtime.h>
#include <cuda_bf16.h>
#include <cstddef>

// LengthRegulator, single fused kernel (R11 theory, resubmission — prior
// attempt hit infra GPUAcquisitionTimeout before running):
//   Block = 32 output frames of one batch, 512 threads (halves the number of
//   redundant scan prologues vs R10's 16-frame blocks).
//   Prologue: 1-element-per-thread warp-shuffle inclusive scan of
//   durations[b] + binary search of the 32 frame source rows into shared.
//   Copy: thread owns column e of 8 CONSECUTIVE frames (L1 line reuse),
//   stores via __stcs (streaming, evict-first — keeps steady-state replay
//   time at the kernel's own duration; proven win in R10).
// B=16, S=512, H=512 fixed; T derived from out_size.

#define LR_B   16
#define LR_S   512
#define LR_V   128        // float4 per row (H=512)
#define LR_FPB 32         // frames per block
#define LR_THR 512

__global__ __launch_bounds__(LR_THR)
void lr_fused_kernel(const float4* __restrict__ x4,
                     const int*    __restrict__ dur,
                     float4*       __restrict__ out4,
                     int T)
{
    __shared__ int cum[LR_S];
    __shared__ int sh_w[16];
    __shared__ int sidx[LR_FPB];

    const int b    = blockIdx.y;
    const int f0   = blockIdx.x * LR_FPB;
    const int tid  = threadIdx.x;
    const int wid  = tid >> 5;       // 0..15
    const int lane = tid & 31;

    // ---- warp-shuffle inclusive scan of durations[b, :] (1 elem/thread) ----
    int v = dur[b * LR_S + tid];
#pragma unroll
    for (int off = 1; off < 32; off <<= 1) {
        int n = __shfl_up_sync(0xFFFFFFFFu, v, off);
        if (lane >= off) v += n;
    }
    if (lane == 31) sh_w[wid] = v;
    __syncthreads();
    if (wid == 0 && lane < 16) {
        int w  = sh_w[lane];
        int vv = w;
#pragma unroll
        for (int off = 1; off < 16; off <<= 1) {
            int n = __shfl_up_sync(0xFFFFu, vv, off);
            if (lane >= off) vv += n;
        }
        sh_w[lane] = vv - w;          // exclusive warp offset
    }
    __syncthreads();
    cum[tid] = v + sh_w[wid];         // inclusive cumsum
    __syncthreads();

    // ---- searchsorted(right) for this block's 32 frames ----
    if (tid < LR_FPB) {
        int t = f0 + tid;
        int lo = 0, hi = LR_S;
        while (lo < hi) {
            int mid = (lo + hi) >> 1;
            if (cum[mid] <= t) lo = mid + 1; else hi = mid;
        }
        sidx[tid] = (lo < LR_S) ? (b * LR_S + lo) : -1;
    }
    __syncthreads();

    // ---- copy: thread = column e of 8 consecutive frames ----
    // g in {0..3}: frames [g*8, g*8+8). Consecutive frames share source rows
    // (avg duration ~7.5) -> most of the 8 loads are L1 same-line hits.
    const int g = tid >> 7;           // 0..3
    const int e = tid & 127;          // vec4 column within row

    float4 val[8];
#pragma unroll
    for (int j = 0; j < 8; j++) {
        int row = sidx[g * 8 + j];
        val[j] = make_float4(0.f, 0.f, 0.f, 0.f);
        if (row >= 0)
            val[j] = __ldg(&x4[(size_t)row * LR_V + e]);
    }

    float4* base = out4 + ((size_t)b * T + f0) * LR_V;
#pragma unroll
    for (int j = 0; j < 8; j++)
        __stcs(&base[(g * 8 + j) * LR_V + e], val[j]);   // streaming store
}

// ---------------- generic fallback (any shape; unused here) ----------------
__global__ void lr_generic_kernel(const float* __restrict__ x,
                                  const int* __restrict__ dur,
                                  float* __restrict__ out,
                                  int B, int S, int H, int T)
{
    size_t i = (size_t)blockIdx.x * blockDim.x + threadIdx.x;
    size_t total = (size_t)B * T * H;
    if (i >= total) return;
    int e = (int)(i % H);
    int t = (int)((i / H) % T);
    int b = (int)(i / ((size_t)T * H));
    int c = 0, idx = S;
    for (int j = 0; j < S; j++) { c += dur[b * S + j]; if (c > t) { idx = j; break; } }
    out[i] = (idx < S) ? x[((size_t)b * S + idx) * H + e] : 0.f;
}

extern "C" void kernel_launch(void* const* d_in, const int* in_sizes, int n_in,
                              void* d_out, int out_size)
{
    const float* x   = (const float*)d_in[0];
    const int*   dur = (const int*)d_in[1];
    float*       out = (float*)d_out;

    const int BS = in_sizes[1];              // B * S = 8192
    const int H  = in_sizes[0] / BS;         // 512
    const int T  = out_size / (LR_B * H);    // 4096
    const int S  = BS / LR_B;

    if (H == 512 && S == LR_S && (T % LR_FPB) == 0) {
        dim3 grid(T / LR_FPB, LR_B);
        lr_fused_kernel<<<grid, LR_THR>>>((const float4*)x, dur,
                                          (float4*)out, T);
    } else {
        size_t total = (size_t)out_size;
        int blocks = (int)((total + 255) / 256);
        lr_generic_kernel<<<blocks, 256>>>(x, dur, out, LR_B, S, H, T);
    }
}